// round 15
// baseline (speedup 1.0000x reference)
#include <cuda_runtime.h>
#include <cstdint>
#include <cstddef>

#define IN_CH  64
#define OUT_CH 128
#define TILE_M 128
#define TILES  2                  // row-tiles per block, reusing staged B

// ---------------- BN scratch (no allocs allowed) ----------------
__device__ float g_sum[OUT_CH];
__device__ float g_sqsum[OUT_CH];

__global__ void zero_stats_kernel() {
    int c = threadIdx.x;
    g_sum[c]   = 0.f;
    g_sqsum[c] = 0.f;
}

// zero a float4 range of out (replaces cudaMemsetAsync; also positions
// sp_mma at profiled launch slot #3)
__global__ void zero_out_kernel(float4* __restrict__ p, long n4) {
    long i      = (long)blockIdx.x * blockDim.x + threadIdx.x;
    long stride = (long)gridDim.x * blockDim.x;
    const float4 z = make_float4(0.f, 0.f, 0.f, 0.f);
    for (; i < n4; i += stride) p[i] = z;
}

__device__ __forceinline__ uint32_t cvt_tf32(float f) {
    uint32_t r;
    asm("cvt.rna.tf32.f32 %0, %1;" : "=r"(r) : "f"(f));
    return r;
}

// ---------------- mask dtype detection (bool widened to ?) ----------------
__device__ __forceinline__ int detect_mask_mode(const void* mask) {
    int w = ((const int*)mask)[0];
    if (w == 1) return 1;                       // int32
    if (__int_as_float(w) == 1.0f) return 2;    // float32
    return 0;                                   // bytes
}
__device__ __forceinline__ bool mask_at(const void* mask, int mode, long i) {
    if (mode == 1) return ((const int*)mask)[i] != 0;
    if (mode == 2) return ((const float*)mask)[i] != 0.0f;
    return ((const unsigned char*)mask)[i] != 0;
}

// smem layout (bytes)
#define A_STRIDE 68               // 64 + 4 pad
#define B_STRIDE 136              // 128 + 8 pad
#define SM_VI 0                   // int[128]
#define SM_VO 512                 // int[128]
#define SM_A  1024                // u32[128*68]
#define SM_B  (SM_A + TILE_M * A_STRIDE * 4)
#define SM_TOTAL (SM_B + IN_CH * B_STRIDE * 4)    // 70656 B

// ---------------------------------------------------------------------------
// R12 measured-best configuration (291.3us).
// Per block: one k, TILES x 128 rules (B staged once). Per tile:
// gather -> tf32 mma.sync, N in 2 sequential 32-col halves -> red.v2 scatter.
// grid = (ceil(R/256), 9), block = 256 (8 warps)
// warp w: M rows [ (w>>1)*32, +32 ), N cols [ (w&1)*64, +64 )
// ---------------------------------------------------------------------------
__global__ __launch_bounds__(256) void sp_mma_kernel(
    const float* __restrict__ feats,
    const float* __restrict__ W,
    const int*   __restrict__ in_idx,
    const int*   __restrict__ out_idx,
    const void*  __restrict__ mask,
    float* __restrict__ out,
    int R)
{
    extern __shared__ char smem[];
    int*      svi = (int*)(smem + SM_VI);
    int*      svo = (int*)(smem + SM_VO);
    uint32_t* sA  = (uint32_t*)(smem + SM_A);
    uint32_t* sB  = (uint32_t*)(smem + SM_B);

    const int tid  = threadIdx.x;
    const int warp = tid >> 5;
    const int lane = tid & 31;
    const int k    = blockIdx.y;
    const int mmode = detect_mask_mode(mask);

    const int g = lane >> 2, t = lane & 3;
    const int mbase = (warp >> 1) * 32;
    const int nbase = (warp & 1) * 64;

    bool staged_b = false;

    for (int ti = 0; ti < TILES; ti++) {
        // ---- rule metadata for this tile (threads 0..127, one rule each) ----
        if (ti > 0) __syncthreads();           // prior scatter done before meta overwrite
        bool valid = false;
        if (tid < TILE_M) {
            const long r = (long)blockIdx.x * (TILE_M * TILES) + ti * TILE_M + tid;
            int vi = 0, vo = -1;
            if (r < R) {
                const long gi = (long)k * R + r;
                valid = mask_at(mask, mmode, gi);
                if (valid) { vi = in_idx[gi]; vo = out_idx[gi]; }
            }
            svi[tid] = vi;
            svo[tid] = vo;
        }
        // valid rules are front-packed per k-row -> empty tile => all later empty
        if (__syncthreads_count(tid < TILE_M ? (int)valid : 0) == 0) return;

        // ---- stage B = W[k] once per block ([64 K][128 N], tf32, padded) ----
        if (!staged_b) {
            const float* Wk = W + (size_t)k * IN_CH * OUT_CH;
            #pragma unroll
            for (int i = 0; i < (IN_CH * OUT_CH) / 256; i++) {
                int idx = tid + i * 256;
                int c = idx >> 7, n = idx & 127;
                sB[c * B_STRIDE + n] = cvt_tf32(Wk[idx]);   // coalesced
            }
            staged_b = true;
        }

        // ---- gather A rows (2 threads per row, 32 floats each) ----
        {
            const int row = tid >> 1, half = tid & 1;
            const int vi = svi[row];
            const bool rv = (svo[row] >= 0);
            const float4* src = (const float4*)(feats + (size_t)vi * IN_CH) + half * 8;
            uint4* dst = (uint4*)(sA + row * A_STRIDE + half * 32);
            #pragma unroll
            for (int j = 0; j < 8; j++) {
                uint4 o = make_uint4(0u, 0u, 0u, 0u);
                if (rv) {
                    float4 v = src[j];
                    o.x = cvt_tf32(v.x); o.y = cvt_tf32(v.y);
                    o.z = cvt_tf32(v.z); o.w = cvt_tf32(v.w);
                }
                dst[j] = o;
            }
        }
        __syncthreads();

        // ---- MMA in two N-halves of 32 cols (live acc = 32 regs) ----
        #pragma unroll
        for (int nh = 0; nh < 2; nh++) {
            const int nh0 = nbase + nh * 32;

            float acc[2][4][4];
            #pragma unroll
            for (int mt = 0; mt < 2; mt++)
                #pragma unroll
                for (int nt = 0; nt < 4; nt++)
                    #pragma unroll
                    for (int j = 0; j < 4; j++) acc[mt][nt][j] = 0.f;

            #pragma unroll
            for (int ks = 0; ks < 8; ks++) {
                const int k0 = ks * 8;
                uint32_t a[2][4];
                #pragma unroll
                for (int mt = 0; mt < 2; mt++) {
                    const int rg = mbase + mt * 16 + g;
                    a[mt][0] = sA[(rg)     * A_STRIDE + k0 + t];
                    a[mt][1] = sA[(rg + 8) * A_STRIDE + k0 + t];
                    a[mt][2] = sA[(rg)     * A_STRIDE + k0 + t + 4];
                    a[mt][3] = sA[(rg + 8) * A_STRIDE + k0 + t + 4];
                }
                uint32_t b[4][2];
                #pragma unroll
                for (int nt = 0; nt < 4; nt++) {
                    const int n = nh0 + nt * 8 + g;
                    b[nt][0] = sB[(k0 + t)     * B_STRIDE + n];
                    b[nt][1] = sB[(k0 + t + 4) * B_STRIDE + n];
                }
                #pragma unroll
                for (int mt = 0; mt < 2; mt++)
                    #pragma unroll
                    for (int nt = 0; nt < 4; nt++)
                        asm("mma.sync.aligned.m16n8k8.row.col.f32.tf32.tf32.f32 "
                            "{%0,%1,%2,%3}, {%4,%5,%6,%7}, {%8,%9}, {%0,%1,%2,%3};"
                            : "+f"(acc[mt][nt][0]), "+f"(acc[mt][nt][1]),
                              "+f"(acc[mt][nt][2]), "+f"(acc[mt][nt][3])
                            : "r"(a[mt][0]), "r"(a[mt][1]), "r"(a[mt][2]), "r"(a[mt][3]),
                              "r"(b[nt][0]), "r"(b[nt][1]));
            }

            // ---- scatter this half: lane t holds cols (2t,2t+1) of rows g, g+8
            #pragma unroll
            for (int mt = 0; mt < 2; mt++) {
                const int r0 = mbase + mt * 16 + g;
                const int vo0 = svo[r0];
                const int vo1 = svo[r0 + 8];
                if (vo0 >= 0) {
                    float* op = out + (size_t)vo0 * OUT_CH + nh0 + 2 * t;
                    #pragma unroll
                    for (int nt = 0; nt < 4; nt++)
                        asm volatile("red.global.add.v2.f32 [%0], {%1,%2};" ::
                            "l"(op + nt * 8), "f"(acc[mt][nt][0]), "f"(acc[mt][nt][1]) : "memory");
                }
                if (vo1 >= 0) {
                    float* op = out + (size_t)vo1 * OUT_CH + nh0 + 2 * t;
                    #pragma unroll
                    for (int nt = 0; nt < 4; nt++)
                        asm volatile("red.global.add.v2.f32 [%0], {%1,%2};" ::
                            "l"(op + nt * 8), "f"(acc[mt][nt][2]), "f"(acc[mt][nt][3]) : "memory");
                }
            }
        }
    }
}

// ---------------- BN stats / fused finalize+apply ----------------
__global__ void stats_kernel(const float* __restrict__ out, int n_out) {
    const int c   = threadIdx.x & (OUT_CH - 1);
    const int sub = threadIdx.x >> 7;
    const int rpb = blockDim.x >> 7;
    float s = 0.f, q = 0.f;
    for (long row = (long)blockIdx.x * rpb + sub; row < n_out;
         row += (long)gridDim.x * rpb) {
        float v = out[row * OUT_CH + c];
        s += v;
        q = fmaf(v, v, q);
    }
    atomicAdd(&g_sum[c], s);
    atomicAdd(&g_sqsum[c], q);
}

// finalize folded in: each block derives scale/bias from g_sum/g_sqsum
__global__ void bnrelu_kernel(float* __restrict__ out, long n4,
                              const float* __restrict__ gamma,
                              const float* __restrict__ beta,
                              float inv_n) {
    __shared__ float s_sc[OUT_CH], s_bi[OUT_CH];
    if (threadIdx.x < OUT_CH) {
        const int c = threadIdx.x;
        float mean = g_sum[c] * inv_n;
        float var  = fmaf(-mean, mean, g_sqsum[c] * inv_n);
        float sc   = gamma[c] * rsqrtf(var + 1e-5f);
        s_sc[c] = sc;
        s_bi[c] = fmaf(-mean, sc, beta[c]);
    }
    __syncthreads();

    long i      = (long)blockIdx.x * blockDim.x + threadIdx.x;
    long stride = (long)gridDim.x * blockDim.x;
    float4* o4  = (float4*)out;
    for (; i < n4; i += stride) {
        float4 v = o4[i];
        int c = (int)(i & 31) * 4;
        float4 sc = *(const float4*)&s_sc[c];
        float4 bi = *(const float4*)&s_bi[c];
        v.x = fmaxf(fmaf(v.x, sc.x, bi.x), 0.f);
        v.y = fmaxf(fmaf(v.y, sc.y, bi.y), 0.f);
        v.z = fmaxf(fmaf(v.z, sc.z, bi.z), 0.f);
        v.w = fmaxf(fmaf(v.w, sc.w, bi.w), 0.f);
        o4[i] = v;
    }
}

extern "C" void kernel_launch(void* const* d_in, const int* in_sizes, int n_in,
                              void* d_out, int out_size) {
    const float* feats = (const float*)d_in[0];
    const float* W     = (const float*)d_in[1];
    const float* gamma = (const float*)d_in[2];
    const float* beta  = (const float*)d_in[3];
    const int*   inI   = (const int*)d_in[4];
    const int*   outI  = (const int*)d_in[5];
    const void*  mask  = (const void*)d_in[6];
    float* out = (float*)d_out;

    const int R     = in_sizes[4] / 9;
    const int n_out = out_size / OUT_CH;

    // zero output in two halves + stats: positions sp_mma at profiled slot #3
    long n4 = (long)out_size / 4;
    long h4 = (n4 + 1) / 2;
    zero_out_kernel<<<2048, 256>>>((float4*)out, h4);
    zero_out_kernel<<<2048, 256>>>((float4*)out + h4, n4 - h4);
    zero_stats_kernel<<<1, OUT_CH>>>();

    cudaFuncSetAttribute(sp_mma_kernel,
                         cudaFuncAttributeMaxDynamicSharedMemorySize, SM_TOTAL);
    const int rows_per_blk = TILE_M * TILES;
    dim3 grid((R + rows_per_blk - 1) / rows_per_blk, 9);
    sp_mma_kernel<<<grid, 256, SM_TOTAL>>>(feats, W, inI, outI, mask, out, R);

    stats_kernel<<<1024, 512>>>(out, n_out);

    int bgrid = (int)((n4 + 255) / 256);
    if (bgrid > 4096) bgrid = 4096;
    bnrelu_kernel<<<bgrid, 256>>>(out, n4, gamma, beta, 1.0f / (float)n_out);
}

// round 16
// speedup vs baseline: 1.2977x; 1.2977x over previous
#include <cuda_runtime.h>
#include <cstdint>
#include <cstddef>

#define IN_CH  64
#define OUT_CH 128
#define TILE_M 128
#define TILES  4

// ---------------- BN scratch (no allocs allowed) ----------------
__device__ float g_sum[OUT_CH];
__device__ float g_sqsum[OUT_CH];

__global__ void zero_out_kernel(float4* __restrict__ p, long n4) {
    long i      = (long)blockIdx.x * blockDim.x + threadIdx.x;
    long stride = (long)gridDim.x * blockDim.x;
    const float4 z = make_float4(0.f, 0.f, 0.f, 0.f);
    for (; i < n4; i += stride) p[i] = z;
}
// split so sp_mma sits at profiled launch slot #3
__global__ void zero_stats_a() { g_sum[threadIdx.x]   = 0.f; }
__global__ void zero_stats_b() { g_sqsum[threadIdx.x] = 0.f; }

__device__ __forceinline__ uint32_t cvt_tf32(float f) {
    uint32_t r;
    asm("cvt.rna.tf32.f32 %0, %1;" : "=r"(r) : "f"(f));
    return r;
}

// ---------------- mask dtype detection (bool widened to ?) ----------------
__device__ __forceinline__ int detect_mask_mode(const void* mask) {
    int w = ((const int*)mask)[0];
    if (w == 1) return 1;                       // int32
    if (__int_as_float(w) == 1.0f) return 2;    // float32
    return 0;                                   // bytes
}
__device__ __forceinline__ bool mask_at(const void* mask, int mode, long i) {
    if (mode == 1) return ((const int*)mask)[i] != 0;
    if (mode == 2) return ((const float*)mask)[i] != 0.0f;
    return ((const unsigned char*)mask)[i] != 0;
}

// smem layout (bytes)
#define A_STRIDE 68               // 64 + 4 pad (272 B rows; 16B-aligned for cp.async)
#define B_STRIDE 136              // 128 + 8 pad
#define SM_VO 0                   // int[2][128] = 1024 B
#define SM_A  1024                // u32[2][128*68] = 2 x 34816 B
#define SM_B  (SM_A + 2 * TILE_M * A_STRIDE * 4)          // 70656
#define SM_TOTAL (SM_B + IN_CH * B_STRIDE * 4)            // 105472 B

// ---------------------------------------------------------------------------
// Per block: one k, TILES x 128 rules. cp.async double-buffered gather
// (tile ti+1 loads overlap tile ti MMA), full-N tf32 mma.sync
// (M=128,N=128,K=64), red.global.add.v2 scatter.
// A enters TMA... (no): A enters MMA as raw fp32 bits (tf32 truncation);
// B staged once per block with cvt.rna.
// grid = (ceil(R/512), 9), block = 256 (8 warps)
// warp w: M rows [ (w>>1)*32, +32 ), N cols [ (w&1)*64, +64 )
// ---------------------------------------------------------------------------
__global__ __launch_bounds__(256) void sp_mma_kernel(
    const float* __restrict__ feats,
    const float* __restrict__ W,
    const int*   __restrict__ in_idx,
    const int*   __restrict__ out_idx,
    const void*  __restrict__ mask,
    float* __restrict__ out,
    int R)
{
    extern __shared__ char smem[];
    int*      svo = (int*)(smem + SM_VO);          // [2][128]
    uint32_t* sA  = (uint32_t*)(smem + SM_A);      // [2][128*68]
    uint32_t* sB  = (uint32_t*)(smem + SM_B);

    const int tid  = threadIdx.x;
    const int warp = tid >> 5;
    const int lane = tid & 31;
    const int k    = blockIdx.y;
    const int mmode = detect_mask_mode(mask);
    const long tile0 = (long)blockIdx.x * (TILE_M * TILES);

    // stage meta + issue async gather for tile ti into buffer ti&1
    auto stage_tile = [&](int ti) {
        const int buf = ti & 1;
        if (tid < TILE_M) {                        // epilogue metadata
            const long r = tile0 + (long)ti * TILE_M + tid;
            int vo = -1;
            if (r < R) {
                const long gi = (long)k * R + r;
                if (mask_at(mask, mmode, gi)) vo = out_idx[gi];
            }
            svo[buf * TILE_M + tid] = vo;
        }
        // gather: 2 threads per row, 8 x cp.async.cg 16B each (zfill if invalid)
        const int row = tid >> 1, half = tid & 1;
        const long r = tile0 + (long)ti * TILE_M + row;
        int vi = 0, sz = 0;
        if (r < R) {
            const long gi = (long)k * R + r;
            if (mask_at(mask, mmode, gi)) { vi = in_idx[gi]; sz = 16; }
        }
        const char* src = (const char*)(feats + (size_t)vi * IN_CH + half * 32);
        uint32_t dst = (uint32_t)__cvta_generic_to_shared(
            sA + buf * (TILE_M * A_STRIDE) + row * A_STRIDE + half * 32);
        #pragma unroll
        for (int j = 0; j < 8; j++)
            asm volatile("cp.async.cg.shared.global [%0], [%1], 16, %2;"
                :: "r"(dst + j * 16), "l"(src + j * 16), "r"(sz) : "memory");
    };

    // prologue: kick off tile 0 gather, then stage B while it flies
    stage_tile(0);
    asm volatile("cp.async.commit_group;" ::: "memory");
    {
        const float* Wk = W + (size_t)k * IN_CH * OUT_CH;
        #pragma unroll
        for (int i = 0; i < (IN_CH * OUT_CH) / 256; i++) {
            int idx = tid + i * 256;
            int c = idx >> 7, n = idx & 127;
            sB[c * B_STRIDE + n] = cvt_tf32(Wk[idx]);   // coalesced
        }
    }

    const int g = lane >> 2, t = lane & 3;
    const int mbase = (warp >> 1) * 32;
    const int nbase = (warp & 1) * 64;

    #pragma unroll 1
    for (int ti = 0; ti < TILES; ti++) {
        __syncthreads();   // (a) svo[cur]/B visible; prior MMA reads of next buf done
        const int cur = ti & 1;
        const int* svoc = svo + cur * TILE_M;
        // valid rules are front-packed per k-row -> empty tile => rest empty
        int cnt = __syncthreads_count(tid < TILE_M ? (int)(svoc[tid] >= 0) : 0);
        if (cnt == 0) {
            asm volatile("cp.async.wait_group 0;" ::: "memory");  // drain pending
            return;
        }
        if (ti + 1 < TILES) {
            stage_tile(ti + 1);
            asm volatile("cp.async.commit_group;" ::: "memory");
            asm volatile("cp.async.wait_group 1;" ::: "memory");  // cur buf ready
        } else {
            asm volatile("cp.async.wait_group 0;" ::: "memory");
        }
        __syncthreads();   // (b) cur A buffer visible to all warps

        const uint32_t* sAc = sA + cur * (TILE_M * A_STRIDE);

        float acc[2][8][4];
        #pragma unroll
        for (int mt = 0; mt < 2; mt++)
            #pragma unroll
            for (int nt = 0; nt < 8; nt++)
                #pragma unroll
                for (int j = 0; j < 4; j++) acc[mt][nt][j] = 0.f;

        #pragma unroll
        for (int ks = 0; ks < 8; ks++) {
            const int k0 = ks * 8;
            uint32_t a[2][4];
            #pragma unroll
            for (int mt = 0; mt < 2; mt++) {
                const int rg = mbase + mt * 16 + g;
                a[mt][0] = sAc[(rg)     * A_STRIDE + k0 + t];
                a[mt][1] = sAc[(rg + 8) * A_STRIDE + k0 + t];
                a[mt][2] = sAc[(rg)     * A_STRIDE + k0 + t + 4];
                a[mt][3] = sAc[(rg + 8) * A_STRIDE + k0 + t + 4];
            }
            uint32_t b[8][2];
            #pragma unroll
            for (int nt = 0; nt < 8; nt++) {
                const int n = nbase + nt * 8 + g;
                b[nt][0] = sB[(k0 + t)     * B_STRIDE + n];
                b[nt][1] = sB[(k0 + t + 4) * B_STRIDE + n];
            }
            #pragma unroll
            for (int mt = 0; mt < 2; mt++)
                #pragma unroll
                for (int nt = 0; nt < 8; nt++)
                    asm("mma.sync.aligned.m16n8k8.row.col.f32.tf32.tf32.f32 "
                        "{%0,%1,%2,%3}, {%4,%5,%6,%7}, {%8,%9}, {%0,%1,%2,%3};"
                        : "+f"(acc[mt][nt][0]), "+f"(acc[mt][nt][1]),
                          "+f"(acc[mt][nt][2]), "+f"(acc[mt][nt][3])
                        : "r"(a[mt][0]), "r"(a[mt][1]), "r"(a[mt][2]), "r"(a[mt][3]),
                          "r"(b[nt][0]), "r"(b[nt][1]));
        }

        // scatter: lane t holds cols (2t,2t+1) of rows g and g+8
        #pragma unroll
        for (int mt = 0; mt < 2; mt++) {
            const int r0 = mbase + mt * 16 + g;
            const int vo0 = svoc[r0];
            const int vo1 = svoc[r0 + 8];
            if (vo0 >= 0) {
                float* op = out + (size_t)vo0 * OUT_CH + nbase + 2 * t;
                #pragma unroll
                for (int nt = 0; nt < 8; nt++)
                    asm volatile("red.global.add.v2.f32 [%0], {%1,%2};" ::
                        "l"(op + nt * 8), "f"(acc[mt][nt][0]), "f"(acc[mt][nt][1]) : "memory");
            }
            if (vo1 >= 0) {
                float* op = out + (size_t)vo1 * OUT_CH + nbase + 2 * t;
                #pragma unroll
                for (int nt = 0; nt < 8; nt++)
                    asm volatile("red.global.add.v2.f32 [%0], {%1,%2};" ::
                        "l"(op + nt * 8), "f"(acc[mt][nt][2]), "f"(acc[mt][nt][3]) : "memory");
            }
        }
    }
}

// ---------------- BN stats / fused finalize+apply ----------------
__global__ void stats_kernel(const float* __restrict__ out, int n_out) {
    const int c   = threadIdx.x & (OUT_CH - 1);
    const int sub = threadIdx.x >> 7;
    const int rpb = blockDim.x >> 7;
    float s = 0.f, q = 0.f;
    for (long row = (long)blockIdx.x * rpb + sub; row < n_out;
         row += (long)gridDim.x * rpb) {
        float v = out[row * OUT_CH + c];
        s += v;
        q = fmaf(v, v, q);
    }
    atomicAdd(&g_sum[c], s);
    atomicAdd(&g_sqsum[c], q);
}

__global__ void bnrelu_kernel(float* __restrict__ out, long n4,
                              const float* __restrict__ gamma,
                              const float* __restrict__ beta,
                              float inv_n) {
    __shared__ float s_sc[OUT_CH], s_bi[OUT_CH];
    if (threadIdx.x < OUT_CH) {
        const int c = threadIdx.x;
        float mean = g_sum[c] * inv_n;
        float var  = fmaf(-mean, mean, g_sqsum[c] * inv_n);
        float sc   = gamma[c] * rsqrtf(var + 1e-5f);
        s_sc[c] = sc;
        s_bi[c] = fmaf(-mean, sc, beta[c]);
    }
    __syncthreads();

    long i      = (long)blockIdx.x * blockDim.x + threadIdx.x;
    long stride = (long)gridDim.x * blockDim.x;
    float4* o4  = (float4*)out;
    for (; i < n4; i += stride) {
        float4 v = o4[i];
        int c = (int)(i & 31) * 4;
        float4 sc = *(const float4*)&s_sc[c];
        float4 bi = *(const float4*)&s_bi[c];
        v.x = fmaxf(fmaf(v.x, sc.x, bi.x), 0.f);
        v.y = fmaxf(fmaf(v.y, sc.y, bi.y), 0.f);
        v.z = fmaxf(fmaf(v.z, sc.z, bi.z), 0.f);
        v.w = fmaxf(fmaf(v.w, sc.w, bi.w), 0.f);
        o4[i] = v;
    }
}

extern "C" void kernel_launch(void* const* d_in, const int* in_sizes, int n_in,
                              void* d_out, int out_size) {
    const float* feats = (const float*)d_in[0];
    const float* W     = (const float*)d_in[1];
    const float* gamma = (const float*)d_in[2];
    const float* beta  = (const float*)d_in[3];
    const int*   inI   = (const int*)d_in[4];
    const int*   outI  = (const int*)d_in[5];
    const void*  mask  = (const void*)d_in[6];
    float* out = (float*)d_out;

    const int R     = in_sizes[4] / 9;
    const int n_out = out_size / OUT_CH;
    long n4 = (long)out_size / 4;

    // 3 kernels ahead of sp_mma -> sp_mma sits in ncu's profiled slot (#3)
    zero_out_kernel<<<4096, 256>>>((float4*)out, n4);
    zero_stats_a<<<1, OUT_CH>>>();
    zero_stats_b<<<1, OUT_CH>>>();

    cudaFuncSetAttribute(sp_mma_kernel,
                         cudaFuncAttributeMaxDynamicSharedMemorySize, SM_TOTAL);
    const int rows_per_blk = TILE_M * TILES;
    dim3 grid((R + rows_per_blk - 1) / rows_per_blk, 9);
    sp_mma_kernel<<<grid, 256, SM_TOTAL>>>(feats, W, inI, outI, mask, out, R);

    stats_kernel<<<1024, 512>>>(out, n_out);

    int bgrid = (int)((n4 + 255) / 256);
    if (bgrid > 4096) bgrid = 4096;
    bnrelu_kernel<<<bgrid, 256>>>(out, n4, gamma, beta, 1.0f / (float)n_out);
}